// round 9
// baseline (speedup 1.0000x reference)
#include <cuda_runtime.h>
#include <cstdint>
#include <math.h>

#define BB 64
#define SEQ 512
#define HH 512
#define DD 256

// Scratch (device globals: no allocation allowed in kernel_launch)
__device__ float g_lt[(size_t)BB * SEQ * DD];   // tanh(lt@W)*diag
__device__ float g_rt[(size_t)BB * SEQ * DD];   // tanh(rt@W)
__device__ float g_wt[(size_t)DD * HH];         // tf32(W^T)  (D,H)

// ---------------------------------------------------------------------------
__device__ __forceinline__ uint32_t f2tf32(float f) {
    uint32_t r; asm("cvt.rna.tf32.f32 %0, %1;" : "=r"(r) : "f"(f)); return r;
}
__device__ __forceinline__ uint32_t smem_u32(const void* p) {
    uint32_t a;
    asm("{ .reg .u64 t; cvta.to.shared.u64 t, %1; cvt.u32.u64 %0, t; }" : "=r"(a) : "l"(p));
    return a;
}
__device__ __forceinline__ void cp16(uint32_t s, const void* g) {
    asm volatile("cp.async.cg.shared.global [%0], [%1], 16;" :: "r"(s), "l"(g));
}
#define CP_COMMIT() asm volatile("cp.async.commit_group;" ::: "memory")
#define CP_WAIT(n)  asm volatile("cp.async.wait_group %0;" :: "n"(n) : "memory")

__device__ __forceinline__ void ldsm_x4(uint32_t* r, uint32_t addr) {
    asm volatile("ldmatrix.sync.aligned.m8n8.x4.shared.b16 {%0,%1,%2,%3}, [%4];"
                 : "=r"(r[0]), "=r"(r[1]), "=r"(r[2]), "=r"(r[3]) : "r"(addr));
}
__device__ __forceinline__ void ldsm_x2(uint32_t* r, uint32_t addr) {
    asm volatile("ldmatrix.sync.aligned.m8n8.x2.shared.b16 {%0,%1}, [%2];"
                 : "=r"(r[0]), "=r"(r[1]) : "r"(addr));
}

// D[16x8] += A[16x8] * B[8x8]  (tf32, row.col; HW truncates fp32->tf32)
__device__ __forceinline__ void mma8(float* d, const uint32_t* a, const uint32_t* b) {
    asm volatile(
        "mma.sync.aligned.m16n8k8.row.col.f32.tf32.tf32.f32 "
        "{%0,%1,%2,%3}, {%4,%5,%6,%7}, {%8,%9}, {%0,%1,%2,%3};"
        : "+f"(d[0]), "+f"(d[1]), "+f"(d[2]), "+f"(d[3])
        : "r"(a[0]), "r"(a[1]), "r"(a[2]), "r"(a[3]), "r"(b[0]), "r"(b[1]));
}

// ---------------------------------------------------------------------------
// Projection GEMM (both lt and rt in one launch).
// CTA tile 128x128, K=512, BK=32, 8 warps (2Mx4N), warp tile 64x32.
// All fragment loads via ldmatrix; no explicit tf32 cvt in mainloop.
// ---------------------------------------------------------------------------
#define PPITCH 36   // 32 data + 4 pad floats (4 mod 32 -> LDSM conflict-free)

__global__ __launch_bounds__(256, 2) void proj_tc(
    const float* __restrict__ lt, const float* __restrict__ rt,
    const float* __restrict__ diag,
    float* __restrict__ Clt, float* __restrict__ Crt)
{
    __shared__ float As[2][128 * PPITCH];
    __shared__ float Bs[2][128 * PPITCH];

    const int tid = threadIdx.x, lane = tid & 31, wid = tid >> 5;
    const int gid = lane >> 2, tig = lane & 3;
    const int wm = wid & 1, wn = wid >> 1;

    const bool is_lt = blockIdx.y < 256;
    const int my = is_lt ? blockIdx.y : (blockIdx.y - 256);
    const float* A = (is_lt ? lt : rt) + (size_t)my * 128 * HH;
    const float* B = g_wt + (size_t)blockIdx.x * 128 * HH;
    float* C = (is_lt ? Clt : Crt) + (size_t)my * 128 * DD + blockIdx.x * 128;

    float acc[4][4][4];
    #pragma unroll
    for (int mt = 0; mt < 4; mt++)
        #pragma unroll
        for (int nt = 0; nt < 4; nt++)
            #pragma unroll
            for (int c = 0; c < 4; c++) acc[mt][nt][c] = 0.f;

    // LDSM lane geometry
    const int rowin  = lane & 7;
    const int asel_r = (lane >> 3) & 1;       // +8 rows for m1,m3
    const int asel_c = (lane >> 4) & 1;       // +4 cols for m2,m3
    const int bsel_c = (lane >> 3) & 1;       // +4 cols for x2 m1
    const uint32_t sA = smem_u32(&As[0][0]);
    const uint32_t sB = smem_u32(&Bs[0][0]);
    // base byte offsets (per buffer = 128*PPITCH*4 bytes)
    const uint32_t aoff0 = ((wm * 64 + asel_r * 8 + rowin) * PPITCH + asel_c * 4) * 4;
    const uint32_t boff0 = ((wn * 32 + rowin) * PPITCH + bsel_c * 4) * 4;
    const uint32_t BUFB = 128 * PPITCH * 4;

    // loader: row = tid>>1 (0..127), half = tid&1 -> 4 float4 chunks at col half*16
    const int r_ld  = tid >> 1;
    const int h_ld  = (tid & 1) * 16;
    auto load_tile = [&](int kt, int buf) {
        const int kb = kt * 32;
        #pragma unroll
        for (int c = 0; c < 4; c++)
            cp16(smem_u32(&As[buf][r_ld * PPITCH + h_ld + c * 4]),
                 A + (size_t)r_ld * HH + kb + h_ld + c * 4);
        #pragma unroll
        for (int c = 0; c < 4; c++)
            cp16(smem_u32(&Bs[buf][r_ld * PPITCH + h_ld + c * 4]),
                 B + (size_t)r_ld * HH + kb + h_ld + c * 4);
        CP_COMMIT();
    };

    constexpr int NK = HH / 32;   // 16
    load_tile(0, 0);

    #pragma unroll 1
    for (int kt = 0; kt < NK; kt++) {
        const int cur = kt & 1;
        if (kt + 1 < NK) { load_tile(kt + 1, cur ^ 1); CP_WAIT(1); }
        else             { CP_WAIT(0); }
        __syncthreads();

        const uint32_t abase = sA + cur * BUFB + aoff0;
        const uint32_t bbase = sB + cur * BUFB + boff0;
        #pragma unroll
        for (int ks = 0; ks < 4; ks++) {
            uint32_t af[4][4], bf[4][2];
            #pragma unroll
            for (int mt = 0; mt < 4; mt++)
                ldsm_x4(af[mt], abase + (mt * 16 * PPITCH + ks * 8) * 4);
            #pragma unroll
            for (int nt = 0; nt < 4; nt++)
                ldsm_x2(bf[nt], bbase + (nt * 8 * PPITCH + ks * 8) * 4);
            #pragma unroll
            for (int mt = 0; mt < 4; mt++)
                #pragma unroll
                for (int nt = 0; nt < 4; nt++)
                    mma8(acc[mt][nt], af[mt], bf[nt]);
        }
        __syncthreads();
    }

    #pragma unroll
    for (int mt = 0; mt < 4; mt++) {
        const int row0 = wm * 64 + mt * 16 + gid;
        #pragma unroll
        for (int nt = 0; nt < 4; nt++) {
            const int col = wn * 32 + nt * 8 + tig * 2;
            float d0 = 1.f, d1 = 1.f;
            if (is_lt) {
                const int gcol = blockIdx.x * 128 + col;
                d0 = __ldg(diag + gcol); d1 = __ldg(diag + gcol + 1);
            }
            float2 v0, v1;
            v0.x = tanhf(acc[mt][nt][0]) * d0;
            v0.y = tanhf(acc[mt][nt][1]) * d1;
            v1.x = tanhf(acc[mt][nt][2]) * d0;
            v1.y = tanhf(acc[mt][nt][3]) * d1;
            *reinterpret_cast<float2*>(C + (size_t)row0 * DD + col) = v0;
            *reinterpret_cast<float2*>(C + (size_t)(row0 + 8) * DD + col) = v1;
        }
    }
}

// ---------------------------------------------------------------------------
// Fused scores + softmax.
// CTA = 64 L-rows x full R=512, K=256.  grid = (SEQ/64, BB).
// A resident in smem (pitch 260); B streamed (BK=16, pitch 20, dbl-buffered);
// scores to 64x516 smem; softmax straight to global out.
// ---------------------------------------------------------------------------
#define PA 260
#define PS 516
#define PB 20
#define FS_SMEM_FLOATS (64 * PA + 64 * PS + 2 * 128 * PB)

__global__ __launch_bounds__(256, 1) void scores_softmax(float* __restrict__ out)
{
    extern __shared__ float sm[];
    float* Ar = sm;                       // 64 x PA
    float* Ss = sm + 64 * PA;             // 64 x PS
    float* Bsm = Ss + 64 * PS;            // 2 x 128 x PB

    const int tid = threadIdx.x, lane = tid & 31, wid = tid >> 5;
    const int gid = lane >> 2, tig = lane & 3;
    const int wm = wid & 1, wn = wid >> 1;
    const int b = blockIdx.y;

    const float* Lt = g_lt + (size_t)b * SEQ * DD + (size_t)blockIdx.x * 64 * DD;
    const float* Rt = g_rt + (size_t)b * SEQ * DD;

    // Resident A: 64 rows x 256 cols; 4 threads/row x 16 float4 chunks
    {
        const int ar = tid >> 2;
        const int ch = tid & 3;
        #pragma unroll
        for (int it = 0; it < 16; it++) {
            const int col = (ch + it * 4) * 4;
            cp16(smem_u32(&Ar[ar * PA + col]), Lt + (size_t)ar * DD + col);
        }
        CP_COMMIT();
    }

    const int r_ld0 = tid >> 2;
    const int kq_ld = tid & 3;
    auto load_b = [&](int nc, int kt, int buf) {
        const int kb = kt * 16;
        #pragma unroll
        for (int j = 0; j < 2; j++) {
            const int r = r_ld0 + j * 64;
            cp16(smem_u32(&Bsm[buf * 128 * PB + r * PB + kq_ld * 4]),
                 Rt + (size_t)(nc * 128 + r) * DD + kb + kq_ld * 4);
        }
        CP_COMMIT();
    };

    // LDSM lane geometry
    const int rowin  = lane & 7;
    const int asel_r = (lane >> 3) & 1;
    const int asel_c = (lane >> 4) & 1;
    const int bsel_c = (lane >> 3) & 1;
    const uint32_t sAr = smem_u32(Ar);
    const uint32_t sBs = smem_u32(Bsm);
    const uint32_t aoff0 = ((wm * 32 + asel_r * 8 + rowin) * PA + asel_c * 4) * 4;
    const uint32_t boff0 = ((wn * 32 + rowin) * PB + bsel_c * 4) * 4;
    const uint32_t BUFB = 128 * PB * 4;

    constexpr int NK = DD / 16;           // 16

    #pragma unroll 1
    for (int nc = 0; nc < 4; nc++) {
        float acc[2][4][4];
        #pragma unroll
        for (int mt = 0; mt < 2; mt++)
            #pragma unroll
            for (int nt = 0; nt < 4; nt++)
                #pragma unroll
                for (int c = 0; c < 4; c++) acc[mt][nt][c] = 0.f;

        load_b(nc, 0, 0);

        #pragma unroll 1
        for (int kt = 0; kt < NK; kt++) {
            const int cur = kt & 1;
            if (kt + 1 < NK) { load_b(nc, kt + 1, cur ^ 1); CP_WAIT(1); }
            else             { CP_WAIT(0); }
            __syncthreads();

            const uint32_t abase = sAr + aoff0 + kt * 16 * 4;
            const uint32_t bbase = sBs + cur * BUFB + boff0;
            #pragma unroll
            for (int ks = 0; ks < 2; ks++) {
                uint32_t af[2][4], bf[4][2];
                #pragma unroll
                for (int mt = 0; mt < 2; mt++)
                    ldsm_x4(af[mt], abase + (mt * 16 * PA + ks * 8) * 4);
                #pragma unroll
                for (int nt = 0; nt < 4; nt++)
                    ldsm_x2(bf[nt], bbase + (nt * 8 * PB + ks * 8) * 4);
                #pragma unroll
                for (int mt = 0; mt < 2; mt++)
                    #pragma unroll
                    for (int nt = 0; nt < 4; nt++)
                        mma8(acc[mt][nt], af[mt], bf[nt]);
            }
            __syncthreads();
        }

        #pragma unroll
        for (int mt = 0; mt < 2; mt++) {
            const int row0 = wm * 32 + mt * 16 + gid;
            #pragma unroll
            for (int nt = 0; nt < 4; nt++) {
                const int col = nc * 128 + wn * 32 + nt * 8 + tig * 2;
                Ss[row0 * PS + col]           = acc[mt][nt][0];
                Ss[row0 * PS + col + 1]       = acc[mt][nt][1];
                Ss[(row0 + 8) * PS + col]     = acc[mt][nt][2];
                Ss[(row0 + 8) * PS + col + 1] = acc[mt][nt][3];
            }
        }
    }
    __syncthreads();

    // softmax: warp w -> rows w*8 .. w*8+7
    const size_t orow0 = ((size_t)b * SEQ + (size_t)blockIdx.x * 64);
    #pragma unroll 1
    for (int rr = 0; rr < 8; rr++) {
        const int row = wid * 8 + rr;
        float4 v[4];
        #pragma unroll
        for (int i = 0; i < 4; i++)
            v[i] = *reinterpret_cast<const float4*>(&Ss[row * PS + lane * 4 + i * 128]);

        float m = -1e30f;
        #pragma unroll
        for (int i = 0; i < 4; i++)
            m = fmaxf(m, fmaxf(fmaxf(v[i].x, v[i].y), fmaxf(v[i].z, v[i].w)));
        #pragma unroll
        for (int off = 16; off; off >>= 1)
            m = fmaxf(m, __shfl_xor_sync(0xffffffffu, m, off));

        float s = 0.f;
        #pragma unroll
        for (int i = 0; i < 4; i++) {
            v[i].x = __expf(v[i].x - m); v[i].y = __expf(v[i].y - m);
            v[i].z = __expf(v[i].z - m); v[i].w = __expf(v[i].w - m);
            s += v[i].x + v[i].y + v[i].z + v[i].w;
        }
        #pragma unroll
        for (int off = 16; off; off >>= 1)
            s += __shfl_xor_sync(0xffffffffu, s, off);
        const float inv = 1.f / s;

        float* op = out + (orow0 + row) * SEQ;
        #pragma unroll
        for (int i = 0; i < 4; i++) {
            float4 o = make_float4(v[i].x * inv, v[i].y * inv, v[i].z * inv, v[i].w * inv);
            *reinterpret_cast<float4*>(op + lane * 4 + i * 128) = o;
        }
    }
}

// ---------------------------------------------------------------------------
// W transpose (H,D) -> (D,H), pre-rounded to tf32.
// ---------------------------------------------------------------------------
__global__ void transpose_w(const float* __restrict__ W, float* __restrict__ Wt) {
    __shared__ float t[32][33];
    const int d0 = blockIdx.x * 32, h0 = blockIdx.y * 32;
    for (int i = threadIdx.y; i < 32; i += 8)
        t[i][threadIdx.x] = W[(size_t)(h0 + i) * DD + d0 + threadIdx.x];
    __syncthreads();
    for (int i = threadIdx.y; i < 32; i += 8)
        Wt[(size_t)(d0 + i) * HH + h0 + threadIdx.x] =
            __uint_as_float(f2tf32(t[threadIdx.x][i]));
}

// ---------------------------------------------------------------------------
extern "C" void kernel_launch(void* const* d_in, const int* in_sizes, int n_in,
                              void* d_out, int out_size)
{
    const float* lt = (const float*)d_in[0];   // (B, L, H)
    const float* rt = (const float*)d_in[1];   // (B, R, H)
    const float* W  = (const float*)d_in[2];   // (H, D)
    const float* dg = (const float*)d_in[3];   // (1, 1, D)
    float* out = (float*)d_out;                // (B, L, R)

    float *p_lt, *p_rt, *p_wt;
    cudaGetSymbolAddress((void**)&p_lt, g_lt);
    cudaGetSymbolAddress((void**)&p_rt, g_rt);
    cudaGetSymbolAddress((void**)&p_wt, g_wt);

    transpose_w<<<dim3(DD / 32, HH / 32), dim3(32, 8)>>>(W, p_wt);

    proj_tc<<<dim3(2, 512), 256>>>(lt, rt, dg, p_lt, p_rt);

    const int FS_BYTES = FS_SMEM_FLOATS * 4;
    cudaFuncSetAttribute(scores_softmax,
                         cudaFuncAttributeMaxDynamicSharedMemorySize, FS_BYTES);
    scores_softmax<<<dim3(SEQ / 64, BB), 256, FS_BYTES>>>(out);
}

// round 10
// speedup vs baseline: 1.1603x; 1.1603x over previous
#include <cuda_runtime.h>
#include <cstdint>
#include <math.h>

#define BB 64
#define SEQ 512
#define HH 512
#define DD 256

// Scratch (device globals: no allocation allowed in kernel_launch)
__device__ float g_lt[(size_t)BB * SEQ * DD];   // tf32(tanh(lt@W)*diag)
__device__ float g_rt[(size_t)BB * SEQ * DD];   // tf32(tanh(rt@W))
__device__ float g_wt[(size_t)DD * HH];         // tf32(W^T)  (D,H)

// ---------------------------------------------------------------------------
__device__ __forceinline__ uint32_t f2tf32(float f) {
    uint32_t r; asm("cvt.rna.tf32.f32 %0, %1;" : "=r"(r) : "f"(f)); return r;
}
__device__ __forceinline__ uint32_t smem_u32(const void* p) {
    uint32_t a;
    asm("{ .reg .u64 t; cvta.to.shared.u64 t, %1; cvt.u32.u64 %0, t; }" : "=r"(a) : "l"(p));
    return a;
}
__device__ __forceinline__ void cp16(uint32_t s, const void* g) {
    asm volatile("cp.async.cg.shared.global [%0], [%1], 16;" :: "r"(s), "l"(g));
}
#define CP_COMMIT() asm volatile("cp.async.commit_group;" ::: "memory")
#define CP_WAIT(n)  asm volatile("cp.async.wait_group %0;" :: "n"(n) : "memory")

__device__ __forceinline__ void ldsm_x4(uint32_t* r, uint32_t addr) {
    asm volatile("ldmatrix.sync.aligned.m8n8.x4.shared.b16 {%0,%1,%2,%3}, [%4];"
                 : "=r"(r[0]), "=r"(r[1]), "=r"(r[2]), "=r"(r[3]) : "r"(addr));
}
__device__ __forceinline__ void ldsm_x2(uint32_t* r, uint32_t addr) {
    asm volatile("ldmatrix.sync.aligned.m8n8.x2.shared.b16 {%0,%1}, [%2];"
                 : "=r"(r[0]), "=r"(r[1]) : "r"(addr));
}

// D[16x8] += A[16x8] * B[8x8]  (tf32, row.col; HW truncates fp32->tf32)
__device__ __forceinline__ void mma8(float* d, const uint32_t* a, const uint32_t* b) {
    asm volatile(
        "mma.sync.aligned.m16n8k8.row.col.f32.tf32.tf32.f32 "
        "{%0,%1,%2,%3}, {%4,%5,%6,%7}, {%8,%9}, {%0,%1,%2,%3};"
        : "+f"(d[0]), "+f"(d[1]), "+f"(d[2]), "+f"(d[3])
        : "r"(a[0]), "r"(a[1]), "r"(a[2]), "r"(a[3]), "r"(b[0]), "r"(b[1]));
}

#define PP 20                      // smem pitch (floats): 16 data + 4 pad
#define PROJ_STAGE (128 * PP)      // floats per matrix per stage
#define PROJ_SMEM_BYTES (4 * 2 * PROJ_STAGE * 4)   // 4 stages x (A+B) = 81920

// ---------------------------------------------------------------------------
// Projection GEMM (lt and rt in one launch).
// CTA tile 128x128, K=512, BK=16, 4-stage cp.async ring, 1 sync per step.
// 8 warps (2Mx4N), warp tile 64x32; ldmatrix fragments.
// ---------------------------------------------------------------------------
__global__ __launch_bounds__(256, 2) void proj_tc(
    const float* __restrict__ lt, const float* __restrict__ rt,
    const float* __restrict__ diag,
    float* __restrict__ Clt, float* __restrict__ Crt)
{
    extern __shared__ float psm[];
    float* As = psm;                      // 4 x 128 x PP
    float* Bs = psm + 4 * PROJ_STAGE;     // 4 x 128 x PP

    const int tid = threadIdx.x, lane = tid & 31, wid = tid >> 5;
    const int gid = lane >> 2, tig = lane & 3;
    const int wm = wid & 1, wn = wid >> 1;

    const bool is_lt = blockIdx.y < 256;
    const int my = is_lt ? blockIdx.y : (blockIdx.y - 256);
    const float* A = (is_lt ? lt : rt) + (size_t)my * 128 * HH;
    const float* B = g_wt + (size_t)blockIdx.x * 128 * HH;
    float* C = (is_lt ? Clt : Crt) + (size_t)my * 128 * DD + blockIdx.x * 128;

    float acc[4][4][4];
    #pragma unroll
    for (int mt = 0; mt < 4; mt++)
        #pragma unroll
        for (int nt = 0; nt < 4; nt++)
            #pragma unroll
            for (int c = 0; c < 4; c++) acc[mt][nt][c] = 0.f;

    // LDSM lane geometry
    const int rowin  = lane & 7;
    const int asel_r = (lane >> 3) & 1;
    const int asel_c = (lane >> 4) & 1;
    const int bsel_c = (lane >> 3) & 1;
    const uint32_t sA = smem_u32(As);
    const uint32_t sB = smem_u32(Bs);
    const uint32_t aoff0 = ((wm * 64 + asel_r * 8 + rowin) * PP + asel_c * 4) * 4;
    const uint32_t boff0 = ((wn * 32 + rowin) * PP + bsel_c * 4) * 4;
    const uint32_t STB = PROJ_STAGE * 4;  // stage bytes

    // loader: 2 threads/row; each does 2 float4 chunks of A and of B
    const int r_ld = tid >> 1;
    const int h_ld = (tid & 1) * 8;
    auto load_tile = [&](int kt) {
        const int buf = kt & 3;
        const int kb = kt * 16;
        float* Ab = As + buf * PROJ_STAGE;
        float* Bb = Bs + buf * PROJ_STAGE;
        #pragma unroll
        for (int c = 0; c < 2; c++) {
            cp16(smem_u32(&Ab[r_ld * PP + h_ld + c * 4]),
                 A + (size_t)r_ld * HH + kb + h_ld + c * 4);
            cp16(smem_u32(&Bb[r_ld * PP + h_ld + c * 4]),
                 B + (size_t)r_ld * HH + kb + h_ld + c * 4);
        }
        CP_COMMIT();
    };

    constexpr int NK = HH / 16;   // 32
    load_tile(0); load_tile(1); load_tile(2);

    #pragma unroll 1
    for (int kt = 0; kt < NK; kt++) {
        CP_WAIT(2);
        __syncthreads();
        if (kt + 3 < NK) load_tile(kt + 3);

        const uint32_t abase = sA + (kt & 3) * STB + aoff0;
        const uint32_t bbase = sB + (kt & 3) * STB + boff0;
        #pragma unroll
        for (int ks = 0; ks < 2; ks++) {
            uint32_t af[4][4], bf[4][2];
            #pragma unroll
            for (int mt = 0; mt < 4; mt++)
                ldsm_x4(af[mt], abase + (mt * 16 * PP + ks * 8) * 4);
            #pragma unroll
            for (int nt = 0; nt < 4; nt++)
                ldsm_x2(bf[nt], bbase + (nt * 8 * PP + ks * 8) * 4);
            #pragma unroll
            for (int mt = 0; mt < 4; mt++)
                #pragma unroll
                for (int nt = 0; nt < 4; nt++)
                    mma8(acc[mt][nt], af[mt], bf[nt]);
        }
    }

    #pragma unroll
    for (int mt = 0; mt < 4; mt++) {
        const int row0 = wm * 64 + mt * 16 + gid;
        #pragma unroll
        for (int nt = 0; nt < 4; nt++) {
            const int col = wn * 32 + nt * 8 + tig * 2;
            float d0 = 1.f, d1 = 1.f;
            if (is_lt) {
                const int gcol = blockIdx.x * 128 + col;
                d0 = __ldg(diag + gcol); d1 = __ldg(diag + gcol + 1);
            }
            float2 v0, v1;
            v0.x = __uint_as_float(f2tf32(tanhf(acc[mt][nt][0]) * d0));
            v0.y = __uint_as_float(f2tf32(tanhf(acc[mt][nt][1]) * d1));
            v1.x = __uint_as_float(f2tf32(tanhf(acc[mt][nt][2]) * d0));
            v1.y = __uint_as_float(f2tf32(tanhf(acc[mt][nt][3]) * d1));
            *reinterpret_cast<float2*>(C + (size_t)row0 * DD + col) = v0;
            *reinterpret_cast<float2*>(C + (size_t)(row0 + 8) * DD + col) = v1;
        }
    }
}

// ---------------------------------------------------------------------------
// Fused scores + softmax, register-resident scores (no smem scores buffer).
// CTA = 64 L-rows x full R=512, K=256.  grid = (SEQ/64, BB).
// A resident in smem; B in a 4-stage cp.async ring; all 128 score values per
// thread live in registers; softmax via shfl + small smem reductions.
// ---------------------------------------------------------------------------
#define PA 260
#define FST (128 * PP)          // floats per B stage
#define FS_SMEM_FLOATS (64 * PA + 4 * FST + 256 + 256)

__global__ __launch_bounds__(256, 1) void scores_softmax(float* __restrict__ out)
{
    extern __shared__ float sm[];
    float* Ar  = sm;                        // 64 x PA
    float* Bsm = sm + 64 * PA;              // 4 x 128 x PP
    float* pm  = Bsm + 4 * FST;             // 64 x 4 partial max
    float* ps  = pm + 256;                  // 64 x 4 partial sum

    const int tid = threadIdx.x, lane = tid & 31, wid = tid >> 5;
    const int gid = lane >> 2, tig = lane & 3;
    const int wm = wid & 1, wn = wid >> 1;
    const int b = blockIdx.y;

    const float* Lt = g_lt + (size_t)b * SEQ * DD + (size_t)blockIdx.x * 64 * DD;
    const float* Rt = g_rt + (size_t)b * SEQ * DD;

    // Resident A: 64 rows x 256 K; 4 threads/row x 16 float4 chunks (full cover)
    {
        const int ar = tid >> 2;
        const int ch = tid & 3;
        #pragma unroll
        for (int it = 0; it < 16; it++) {
            const int col = ch * 4 + it * 16;
            cp16(smem_u32(&Ar[ar * PA + col]), Lt + (size_t)ar * DD + col);
        }
        CP_COMMIT();
    }

    const int r_ld0 = tid >> 2;
    const int kq_ld = tid & 3;
    auto load_b = [&](int j) {              // j = global tile index 0..63
        const int nc = j >> 4, kt = j & 15, buf = j & 3;
        const int kb = kt * 16;
        #pragma unroll
        for (int jj = 0; jj < 2; jj++) {
            const int r = r_ld0 + jj * 64;
            cp16(smem_u32(&Bsm[buf * FST + r * PP + kq_ld * 4]),
                 Rt + (size_t)(nc * 128 + r) * DD + kb + kq_ld * 4);
        }
        CP_COMMIT();
    };

    // LDSM lane geometry
    const int rowin  = lane & 7;
    const int asel_r = (lane >> 3) & 1;
    const int asel_c = (lane >> 4) & 1;
    const int bsel_c = (lane >> 3) & 1;
    const uint32_t sAr = smem_u32(Ar);
    const uint32_t sBs = smem_u32(Bsm);
    const uint32_t aoff0 = ((wm * 32 + asel_r * 8 + rowin) * PA + asel_c * 4) * 4;
    const uint32_t boff0 = ((wn * 32 + rowin) * PP + bsel_c * 4) * 4;
    const uint32_t STB = FST * 4;

    load_b(0); load_b(1); load_b(2);

    float acc[4][2][4][4];                  // [nc][mt][nt][c] — all static-indexed
    #pragma unroll
    for (int nc = 0; nc < 4; nc++)
        #pragma unroll
        for (int mt = 0; mt < 2; mt++)
            #pragma unroll
            for (int nt = 0; nt < 4; nt++)
                #pragma unroll
                for (int c = 0; c < 4; c++) acc[nc][mt][nt][c] = 0.f;

    #pragma unroll
    for (int nc = 0; nc < 4; nc++) {
        #pragma unroll 1
        for (int kt = 0; kt < 16; kt++) {
            const int i = nc * 16 + kt;
            CP_WAIT(2);
            __syncthreads();
            if (i + 3 < 64) load_b(i + 3);

            const uint32_t abase = sAr + aoff0 + (uint32_t)kt * 16 * 4;
            const uint32_t bbase = sBs + (uint32_t)(i & 3) * STB + boff0;
            #pragma unroll
            for (int ks = 0; ks < 2; ks++) {
                uint32_t af[2][4], bf[4][2];
                #pragma unroll
                for (int mt = 0; mt < 2; mt++)
                    ldsm_x4(af[mt], abase + (mt * 16 * PA + ks * 8) * 4);
                #pragma unroll
                for (int nt = 0; nt < 4; nt++)
                    ldsm_x2(bf[nt], bbase + (nt * 8 * PP + ks * 8) * 4);
                #pragma unroll
                for (int mt = 0; mt < 2; mt++)
                    #pragma unroll
                    for (int nt = 0; nt < 4; nt++)
                        mma8(acc[nc][mt][nt], af[mt], bf[nt]);
            }
        }
    }

    // ---- softmax on register-resident scores ----
    // Thread owns rows: wm*32 + mt*16 + d*8 + gid  (mt,d in {0,1})
    // and cols: nc*128 + wn*32 + nt*8 + tig*2 + {0,1}
    __syncthreads();   // before reusing smem region pm/ps (safe: distinct region, cheap)

    // 1) global max per row
    float gm[2][2];
    #pragma unroll
    for (int mt = 0; mt < 2; mt++)
        #pragma unroll
        for (int d = 0; d < 2; d++) {
            float lm = -1e30f;
            #pragma unroll
            for (int nc = 0; nc < 4; nc++)
                #pragma unroll
                for (int nt = 0; nt < 4; nt++)
                    lm = fmaxf(lm, fmaxf(acc[nc][mt][nt][d * 2], acc[nc][mt][nt][d * 2 + 1]));
            lm = fmaxf(lm, __shfl_xor_sync(0xffffffffu, lm, 1));
            lm = fmaxf(lm, __shfl_xor_sync(0xffffffffu, lm, 2));
            const int row = wm * 32 + mt * 16 + d * 8 + gid;
            if (tig == 0) pm[row * 4 + wn] = lm;
        }
    __syncthreads();
    #pragma unroll
    for (int mt = 0; mt < 2; mt++)
        #pragma unroll
        for (int d = 0; d < 2; d++) {
            const int row = wm * 32 + mt * 16 + d * 8 + gid;
            gm[mt][d] = fmaxf(fmaxf(pm[row * 4 + 0], pm[row * 4 + 1]),
                              fmaxf(pm[row * 4 + 2], pm[row * 4 + 3]));
        }

    // 2) exp in place + global sum per row
    #pragma unroll
    for (int mt = 0; mt < 2; mt++)
        #pragma unroll
        for (int d = 0; d < 2; d++) {
            float lsum = 0.f;
            const float m = gm[mt][d];
            #pragma unroll
            for (int nc = 0; nc < 4; nc++)
                #pragma unroll
                for (int nt = 0; nt < 4; nt++) {
                    float e0 = __expf(acc[nc][mt][nt][d * 2]     - m);
                    float e1 = __expf(acc[nc][mt][nt][d * 2 + 1] - m);
                    acc[nc][mt][nt][d * 2]     = e0;
                    acc[nc][mt][nt][d * 2 + 1] = e1;
                    lsum += e0 + e1;
                }
            lsum += __shfl_xor_sync(0xffffffffu, lsum, 1);
            lsum += __shfl_xor_sync(0xffffffffu, lsum, 2);
            const int row = wm * 32 + mt * 16 + d * 8 + gid;
            if (tig == 0) ps[row * 4 + wn] = lsum;
        }
    __syncthreads();

    // 3) scale + write out
    const size_t orow0 = ((size_t)b * SEQ + (size_t)blockIdx.x * 64);
    #pragma unroll
    for (int mt = 0; mt < 2; mt++)
        #pragma unroll
        for (int d = 0; d < 2; d++) {
            const int row = wm * 32 + mt * 16 + d * 8 + gid;
            const float inv = 1.f / (ps[row * 4 + 0] + ps[row * 4 + 1] +
                                     ps[row * 4 + 2] + ps[row * 4 + 3]);
            float* op = out + (orow0 + row) * SEQ;
            #pragma unroll
            for (int nc = 0; nc < 4; nc++)
                #pragma unroll
                for (int nt = 0; nt < 4; nt++) {
                    const int col = nc * 128 + wn * 32 + nt * 8 + tig * 2;
                    float2 v;
                    v.x = acc[nc][mt][nt][d * 2]     * inv;
                    v.y = acc[nc][mt][nt][d * 2 + 1] * inv;
                    *reinterpret_cast<float2*>(op + col) = v;
                }
        }
}

// ---------------------------------------------------------------------------
// W transpose (H,D) -> (D,H), pre-rounded to tf32.
// ---------------------------------------------------------------------------
__global__ void transpose_w(const float* __restrict__ W, float* __restrict__ Wt) {
    __shared__ float t[32][33];
    const int d0 = blockIdx.x * 32, h0 = blockIdx.y * 32;
    for (int i = threadIdx.y; i < 32; i += 8)
        t[i][threadIdx.x] = W[(size_t)(h0 + i) * DD + d0 + threadIdx.x];
    __syncthreads();
    for (int i = threadIdx.y; i < 32; i += 8)
        Wt[(size_t)(d0 + i) * HH + h0 + threadIdx.x] =
            __uint_as_float(f2tf32(t[threadIdx.x][i]));
}

// ---------------------------------------------------------------------------
extern "C" void kernel_launch(void* const* d_in, const int* in_sizes, int n_in,
                              void* d_out, int out_size)
{
    const float* lt = (const float*)d_in[0];   // (B, L, H)
    const float* rt = (const float*)d_in[1];   // (B, R, H)
    const float* W  = (const float*)d_in[2];   // (H, D)
    const float* dg = (const float*)d_in[3];   // (1, 1, D)
    float* out = (float*)d_out;                // (B, L, R)

    float *p_lt, *p_rt, *p_wt;
    cudaGetSymbolAddress((void**)&p_lt, g_lt);
    cudaGetSymbolAddress((void**)&p_rt, g_rt);
    cudaGetSymbolAddress((void**)&p_wt, g_wt);

    transpose_w<<<dim3(DD / 32, HH / 32), dim3(32, 8)>>>(W, p_wt);

    cudaFuncSetAttribute(proj_tc, cudaFuncAttributeMaxDynamicSharedMemorySize,
                         PROJ_SMEM_BYTES);
    proj_tc<<<dim3(2, 512), 256, PROJ_SMEM_BYTES>>>(lt, rt, dg, p_lt, p_rt);

    const int FS_BYTES = FS_SMEM_FLOATS * 4;   // 109568
    cudaFuncSetAttribute(scores_softmax,
                         cudaFuncAttributeMaxDynamicSharedMemorySize, FS_BYTES);
    scores_softmax<<<dim3(SEQ / 64, BB), 256, FS_BYTES>>>(out);
}